// round 8
// baseline (speedup 1.0000x reference)
#include <cuda_runtime.h>
#include <cstdint>

// ---------------- problem constants (fixed-shape problem) ----------------
constexpr int NN   = 10000;  // nodes
constexpr int F1   = 64;     // hidden feat
constexpr int COUT = 16;     // classes

// GEMM1 (mma.sync tf32, fragment-order smem) tiling
constexpr int BM    = 128;
constexpr int BK    = 16;
constexpr int SPLIT = 4;
constexpr int NCH   = NN / BK;   // 625 exact
constexpr int LDRAW = 20;        // padded raw-A k-stride (floats)

// dynamic smem layout (floats)
constexpr int RAW_OFF   = 0;                    // rawA[2][128*20]
constexpr int RAW_STG   = BM * LDRAW;           // 2560
constexpr int BFRAG_OFF = 2 * RAW_STG;          // 5120
constexpr int BFRAG_STG = 2048;                 // 16 blocks x 32 lanes x 4
constexpr int AFRAG_OFF = BFRAG_OFF + 2 * BFRAG_STG;  // 9216
constexpr int AFRAG_SZ  = 4096;                 // 16 blocks x 32 lanes x 8
constexpr int SMEM_FLOATS = AFRAG_OFF + AFRAG_SZ;     // 13312 -> 53248 B

// ---------------- device scratch (no allocation; device-code refs only) --
__device__ __align__(16) float g_deg[NN];
__device__ __align__(16) float g_dinv[NN];
__device__ __align__(16) float g_bufA[(size_t)NN * F1];
__device__ __align__(16) float g_bufB[(size_t)NN * F1];
__device__ __align__(16) float g_part[(size_t)SPLIT * NN * F1];
__device__ __align__(16) float g_wfrag[(size_t)NCH * 2048];  // B fragments hi/lo

__device__ __forceinline__ int clampN(int v) {
    v = v < 0 ? 0 : v;
    return v < NN ? v : NN - 1;
}

// ---------------- PTX helpers ----------------
__device__ __forceinline__ uint32_t tf32_rna(float f) {
    uint32_t u;
    asm("cvt.rna.tf32.f32 %0, %1;" : "=r"(u) : "f"(f));
    return u;
}
__device__ __forceinline__ void tf32split(float a, uint32_t& hi, uint32_t& lo) {
    hi = tf32_rna(a);
    lo = tf32_rna(a - __uint_as_float(hi));
}
__device__ __forceinline__ void mma8(float* d, const uint32_t* a, const uint32_t* b) {
    asm volatile(
        "mma.sync.aligned.m16n8k8.row.col.f32.tf32.tf32.f32 "
        "{%0,%1,%2,%3},{%4,%5,%6,%7},{%8,%9},{%0,%1,%2,%3};"
        : "+f"(d[0]), "+f"(d[1]), "+f"(d[2]), "+f"(d[3])
        : "r"(a[0]), "r"(a[1]), "r"(a[2]), "r"(a[3]), "r"(b[0]), "r"(b[1]));
}
__device__ __forceinline__ void cp16(uint32_t dst, const void* src) {
    asm volatile("cp.async.cg.shared.global [%0], [%1], 16;" :: "r"(dst), "l"(src));
}

// ---------------- degree / norm ----------------
__global__ void deg_init_kernel() {
    int i = blockIdx.x * blockDim.x + threadIdx.x;
    if (i < NN) g_deg[i] = 1.0f;
}
__global__ void deg_count_kernel(const int* __restrict__ ei, int E) {
    int e = blockIdx.x * blockDim.x + threadIdx.x;
    if (e < E) atomicAdd(&g_deg[clampN(ei[E + e])], 1.0f);
}
__global__ void dinv_kernel() {
    int i = blockIdx.x * blockDim.x + threadIdx.x;
    if (i < NN) g_dinv[i] = rsqrtf(g_deg[i]);
}

// ---------------- W1 -> fragment-order hi/lo (g_wfrag) ----------------
// For chunk c, k8, n8, lane(g,t): float4 {hi(W[k0][n]), hi(W[k0+4][n]),
//                                         lo(W[k0][n]), lo(W[k0+4][n])}
__global__ void wfrag_kernel(const float* __restrict__ W) {
    int idx = blockIdx.x * blockDim.x + threadIdx.x;
    if (idx >= NCH * 512) return;
    const int lane = idx & 31;
    const int n8   = (idx >> 5) & 7;
    const int k8   = (idx >> 8) & 1;
    const int c    = idx >> 9;
    const int g = lane >> 2, t = lane & 3;
    const int n  = n8 * 8 + g;
    const int k0 = c * 16 + k8 * 8 + t;
    const float w0 = W[(size_t)k0 * 64 + n];
    const float w1 = W[(size_t)(k0 + 4) * 64 + n];
    uint32_t h0, l0, h1, l1;
    tf32split(w0, h0, l0);
    tf32split(w1, h1, l1);
    float4 v = make_float4(__uint_as_float(h0), __uint_as_float(h1),
                           __uint_as_float(l0), __uint_as_float(l1));
    reinterpret_cast<float4*>(g_wfrag)[idx] = v;
}

// ---------------- GEMM1: mma.sync tf32 hi/lo, fragment smem, split-K -----
__global__ void __launch_bounds__(256, 2) gemm1_mma_kernel(const float* __restrict__ A) {
    extern __shared__ __align__(16) float smf[];
    float4* aFrag4 = reinterpret_cast<float4*>(&smf[AFRAG_OFF]);

    const int tid  = threadIdx.x;
    const int lane = tid & 31;
    const int wid  = tid >> 5;
    const int g    = lane >> 2;
    const int t    = lane & 3;
    const int wm   = wid >> 2;         // 0..1 (64-row half)
    const int wn   = wid & 3;          // 0..3 (16-col strip)
    const int m0   = blockIdx.x * BM;
    const int part = blockIdx.y;

    const int q = NCH / SPLIT, r = NCH % SPLIT;
    const int cBeg = part * q + (part < r ? part : r);
    const int nCh  = q + (part < r ? 1 : 0);

    // loader task mapping (2 rawA + 2 bFrag cp16 per thread per chunk)
    const int taskA0 = tid, taskA1 = tid + 256;    // 512 A tasks
    const int am0 = taskA0 >> 2, aj0 = (taskA0 & 3) * 4;
    const int am1 = taskA1 >> 2, aj1 = (taskA1 & 3) * 4;
    const float* Ap0 = A + (size_t)clampN(m0 + am0) * NN + aj0;
    const float* Ap1 = A + (size_t)clampN(m0 + am1) * NN + aj1;

    const uint32_t sbase = (uint32_t)__cvta_generic_to_shared(smf);
    const uint32_t rawB  = sbase + RAW_OFF * 4;
    const uint32_t bfB   = sbase + BFRAG_OFF * 4;
    const uint32_t aDst0 = rawB + (uint32_t)(am0 * LDRAW + aj0) * 4;
    const uint32_t aDst1 = rawB + (uint32_t)(am1 * LDRAW + aj1) * 4;

    float acc[4][2][4] = {};   // [msub][nsub][reg]

    // prologue: chunk cBeg -> stage 0
    {
        const size_t kf = (size_t)cBeg * BK;
        cp16(aDst0, Ap0 + kf);
        cp16(aDst1, Ap1 + kf);
        const float* bsrc = &g_wfrag[(size_t)cBeg * 2048];
        cp16(bfB + (uint32_t)tid * 16,         bsrc + tid * 4);
        cp16(bfB + (uint32_t)(tid + 256) * 16, bsrc + (tid + 256) * 4);
        asm volatile("cp.async.commit_group;");
    }

    for (int i = 0; i < nCh; ++i) {
        const int s = i & 1;
        if (i + 1 < nCh) {
            const int ns = s ^ 1;
            const size_t kf = (size_t)(cBeg + i + 1) * BK;
            cp16(aDst0 + ns * RAW_STG * 4, Ap0 + kf);
            cp16(aDst1 + ns * RAW_STG * 4, Ap1 + kf);
            const float* bsrc = &g_wfrag[(size_t)(cBeg + i + 1) * 2048];
            cp16(bfB + (uint32_t)(ns * BFRAG_STG + tid * 4) * 4,         bsrc + tid * 4);
            cp16(bfB + (uint32_t)(ns * BFRAG_STG + (tid + 256) * 4) * 4, bsrc + (tid + 256) * 4);
            asm volatile("cp.async.commit_group;");
            asm volatile("cp.async.wait_group 1;");
        } else {
            asm volatile("cp.async.wait_group 0;");
        }
        __syncthreads();   // rawA/bFrag(s) ready; prev compute done (aFrag free)

        // ---- convert: rawA(s) -> aFrag (hi/lo, fragment order), once per elem
        {
            const float* raw = &smf[RAW_OFF + s * RAW_STG];
            #pragma unroll
            for (int bb = 0; bb < 2; ++bb) {
                const int blk  = wid * 2 + bb;       // 0..15 = k8*8 + msub
                const int k8c  = blk >> 3;
                const int msub = blk & 7;
                const int m = msub * 16 + g;
                const int k = k8c * 8 + t;
                const float a00 = raw[m * LDRAW + k];
                const float a10 = raw[(m + 8) * LDRAW + k];
                const float a01 = raw[m * LDRAW + k + 4];
                const float a11 = raw[(m + 8) * LDRAW + k + 4];
                uint32_t h[4], l[4];
                tf32split(a00, h[0], l[0]);
                tf32split(a10, h[1], l[1]);
                tf32split(a01, h[2], l[2]);
                tf32split(a11, h[3], l[3]);
                float4 hv = make_float4(__uint_as_float(h[0]), __uint_as_float(h[1]),
                                        __uint_as_float(h[2]), __uint_as_float(h[3]));
                float4 lv = make_float4(__uint_as_float(l[0]), __uint_as_float(l[1]),
                                        __uint_as_float(l[2]), __uint_as_float(l[3]));
                aFrag4[blk * 64 + lane * 2]     = hv;
                aFrag4[blk * 64 + lane * 2 + 1] = lv;
            }
        }
        __syncthreads();

        // ---- compute: pure LDS.128 + MMA
        const float4* bF = reinterpret_cast<const float4*>(&smf[BFRAG_OFF + s * BFRAG_STG]);
        #pragma unroll
        for (int k8 = 0; k8 < 2; ++k8) {
            float4 bv[2];
            #pragma unroll
            for (int ns = 0; ns < 2; ++ns)
                bv[ns] = bF[(k8 * 8 + wn * 2 + ns) * 32 + lane];
            #pragma unroll
            for (int ms = 0; ms < 4; ++ms) {
                const int blk = k8 * 8 + wm * 4 + ms;
                const float4 hv = aFrag4[blk * 64 + lane * 2];
                const float4 lv = aFrag4[blk * 64 + lane * 2 + 1];
                uint32_t ah[4] = {__float_as_uint(hv.x), __float_as_uint(hv.y),
                                  __float_as_uint(hv.z), __float_as_uint(hv.w)};
                uint32_t al[4] = {__float_as_uint(lv.x), __float_as_uint(lv.y),
                                  __float_as_uint(lv.z), __float_as_uint(lv.w)};
                #pragma unroll
                for (int ns = 0; ns < 2; ++ns) {
                    uint32_t bh[2] = {__float_as_uint(bv[ns].x), __float_as_uint(bv[ns].y)};
                    uint32_t bl[2] = {__float_as_uint(bv[ns].z), __float_as_uint(bv[ns].w)};
                    mma8(acc[ms][ns], ah, bh);   // hi*hi
                    mma8(acc[ms][ns], ah, bl);   // hi*lo
                    mma8(acc[ms][ns], al, bh);   // lo*hi
                }
            }
        }
        __syncthreads();
    }

    // epilogue -> g_part[part] (mapping verified in round 7)
    float* outp = &g_part[(size_t)part * NN * F1];
    #pragma unroll
    for (int ms = 0; ms < 4; ++ms) {
        #pragma unroll
        for (int ns = 0; ns < 2; ++ns) {
            const int col = wn * 16 + ns * 8 + 2 * t;
            const int r0  = m0 + wm * 64 + ms * 16 + g;
            if (r0 < NN) {
                float2 v0 = make_float2(acc[ms][ns][0], acc[ms][ns][1]);
                *reinterpret_cast<float2*>(&outp[(size_t)r0 * F1 + col]) = v0;
            }
            const int r1 = r0 + 8;
            if (r1 < NN) {
                float2 v1 = make_float2(acc[ms][ns][2], acc[ms][ns][3]);
                *reinterpret_cast<float2*>(&outp[(size_t)r1 * F1 + col]) = v1;
            }
        }
    }
}

// reduce split-K partials -> g_bufA, fused self-loop init -> g_bufB
__global__ void reduce_agg_kernel() {
    int idx4 = blockIdx.x * blockDim.x + threadIdx.x;
    if (idx4 < NN * F1 / 4) {
        float4 s = make_float4(0.f, 0.f, 0.f, 0.f);
        #pragma unroll
        for (int p = 0; p < SPLIT; ++p) {
            const float4 v = *reinterpret_cast<const float4*>(
                &g_part[(size_t)p * NN * F1 + (size_t)idx4 * 4]);
            s.x += v.x; s.y += v.y; s.z += v.z; s.w += v.w;
        }
        *reinterpret_cast<float4*>(&g_bufA[(size_t)idx4 * 4]) = s;
        const int row = idx4 / (F1 / 4);
        const float d  = g_dinv[row];
        const float d2 = d * d;
        float4 tt = make_float4(s.x * d2, s.y * d2, s.z * d2, s.w * d2);
        *reinterpret_cast<float4*>(&g_bufB[(size_t)idx4 * 4]) = tt;
    }
}

// ---------------- small GEMMs: g_bufB [NN,64] x W [64,C] -> g_bufA --------
template <int CIN, int C>
__global__ void gemm_small_agg_kernel(const float* __restrict__ W) {
    __shared__ float w_s[CIN * C];
    for (int i = threadIdx.x; i < CIN * C; i += blockDim.x) w_s[i] = W[i];
    __syncthreads();
    const int total  = NN * C;
    const int stride = gridDim.x * blockDim.x;
    for (int idx = blockIdx.x * blockDim.x + threadIdx.x; idx < total; idx += stride) {
        const int row = idx / C;
        const int col = idx % C;
        const float* rp = &g_bufB[(size_t)row * CIN];
        float acc = 0.0f;
        #pragma unroll
        for (int k = 0; k < CIN; ++k) acc += rp[k] * w_s[k * C + col];
        g_bufA[idx] = acc;
    }
}

// self-loop init for layers 2/3
template <int C>
__global__ void agg_init_kernel() {
    int idx4 = blockIdx.x * blockDim.x + threadIdx.x;
    if (idx4 < NN * C / 4) {
        const int row = idx4 / (C / 4);
        const float d  = g_dinv[row];
        const float d2 = d * d;
        const float4 v = *reinterpret_cast<const float4*>(&g_bufA[(size_t)idx4 * 4]);
        float4 tt = make_float4(v.x * d2, v.y * d2, v.z * d2, v.w * d2);
        *reinterpret_cast<float4*>(&g_bufB[(size_t)idx4 * 4]) = tt;
    }
}

// edges: one thread per (edge, 4-col group): float4 gather + red.v4
template <int C>
__global__ void agg_edges_kernel(const int* __restrict__ ei, int E) {
    constexpr int LPE = C / 4;
    const long long t = (long long)blockIdx.x * blockDim.x + threadIdx.x;
    if (t >= (long long)E * LPE) return;
    const int e = (int)(t / LPE);
    const int g = (int)(t % LPE);
    const int src = clampN(ei[e]);
    const int dst = clampN(ei[E + e]);
    const float norm = g_dinv[src] * g_dinv[dst];
    const float4 v = *reinterpret_cast<const float4*>(&g_bufA[(size_t)src * C + g * 4]);
    float* o = &g_bufB[(size_t)dst * C + g * 4];
    asm volatile("red.global.add.v4.f32 [%0], {%1, %2, %3, %4};"
                 :: "l"(o), "f"(v.x * norm), "f"(v.y * norm),
                    "f"(v.z * norm), "f"(v.w * norm)
                 : "memory");
}

// ---------------- epilogues ----------------
template <int C>
__global__ void bias_relu_kernel(const float* __restrict__ b) {
    int idx4 = blockIdx.x * blockDim.x + threadIdx.x;
    if (idx4 < NN * C / 4) {
        const float4 bb = *reinterpret_cast<const float4*>(&b[(idx4 % (C / 4)) * 4]);
        float4 v = *reinterpret_cast<float4*>(&g_bufB[(size_t)idx4 * 4]);
        v.x = fmaxf(v.x + bb.x, 0.f);
        v.y = fmaxf(v.y + bb.y, 0.f);
        v.z = fmaxf(v.z + bb.z, 0.f);
        v.w = fmaxf(v.w + bb.w, 0.f);
        *reinterpret_cast<float4*>(&g_bufB[(size_t)idx4 * 4]) = v;
    }
}

__global__ void softmax_kernel(const float* __restrict__ b, float* __restrict__ out) {
    int r = blockIdx.x * blockDim.x + threadIdx.x;
    if (r >= NN) return;
    float v[COUT];
    float m = -1e30f;
    #pragma unroll
    for (int j = 0; j < COUT; ++j) {
        v[j] = g_bufB[(size_t)r * COUT + j] + b[j];
        m = fmaxf(m, v[j]);
    }
    float s = 0.0f;
    #pragma unroll
    for (int j = 0; j < COUT; ++j) {
        v[j] = expf(v[j] - m);
        s += v[j];
    }
    const float inv = 1.0f / s;
    #pragma unroll
    for (int j = 0; j < COUT; ++j) out[(size_t)r * COUT + j] = v[j] * inv;
}

// ---------------- launch ----------------
extern "C" void kernel_launch(void* const* d_in, const int* in_sizes, int n_in,
                              void* d_out, int out_size) {
    const float* x  = (const float*)d_in[0];
    const int*   ei = (const int*)d_in[1];   // int32 (JAX x64 disabled)
    const float* W1 = (const float*)d_in[2];
    const float* b1 = (const float*)d_in[3];
    const float* W2 = (const float*)d_in[4];
    const float* b2 = (const float*)d_in[5];
    const float* W3 = (const float*)d_in[6];
    const float* b3 = (const float*)d_in[7];
    float* out = (float*)d_out;

    const int E = in_sizes[1] / 2;

    static bool attr_done = false;
    if (!attr_done) {
        cudaFuncSetAttribute(gemm1_mma_kernel,
                             cudaFuncAttributeMaxDynamicSharedMemorySize,
                             SMEM_FLOATS * 4);
        attr_done = true;
    }

    const int T = 256;
    const int gN    = (NN + T - 1) / T;
    const int gE    = (E + T - 1) / T;
    const int g64v  = (NN * F1 / 4 + T - 1) / T;
    const int g16v  = (NN * COUT / 4 + T - 1) / T;
    const int gE64  = (int)(((long long)E * (F1 / 4) + T - 1) / T);
    const int gE16  = (int)(((long long)E * (COUT / 4) + T - 1) / T);
    const dim3 gG((NN + BM - 1) / BM, SPLIT);   // 79 x 4

    // degrees + normalization + W1 prep
    deg_init_kernel<<<gN, T>>>();
    deg_count_kernel<<<gE, T>>>(ei, E);
    dinv_kernel<<<gN, T>>>();
    wfrag_kernel<<<(NCH * 512 + T - 1) / T, T>>>(W1);

    // ---- layer 1 ----
    gemm1_mma_kernel<<<gG, 256, SMEM_FLOATS * 4>>>(x);
    reduce_agg_kernel<<<g64v, T>>>();              // bufA = sum parts, bufB = self-loop
    agg_edges_kernel<F1><<<gE64, T>>>(ei, E);
    bias_relu_kernel<F1><<<g64v, T>>>(b1);

    // ---- layer 2 ----
    gemm_small_agg_kernel<F1, F1><<<1480, T>>>(W2);
    agg_init_kernel<F1><<<g64v, T>>>();
    agg_edges_kernel<F1><<<gE64, T>>>(ei, E);
    bias_relu_kernel<F1><<<g64v, T>>>(b2);

    // ---- layer 3 ----
    gemm_small_agg_kernel<F1, COUT><<<1480, T>>>(W3);
    agg_init_kernel<COUT><<<g16v, T>>>();
    agg_edges_kernel<COUT><<<gE16, T>>>(ei, E);
    softmax_kernel<<<gN, T>>>(b3, out);
}